// round 12
// baseline (speedup 1.0000x reference)
#include <cuda_runtime.h>
#include <cuda_fp16.h>
#include <cstdint>

#define NN 2048
#define FF 64
#define HH 128
#define TI 32
#define NB (NN/TI)            // 64
#define NPAIR (NB*(NB+1)/2)   // 2080
#define EDGEF 2096128.0       // NN*(NN-1)/2
#define ES ((size_t)NPAIR*1024)   // 2,129,920 edge slots

typedef unsigned int u32;

// ---------------- scratch ----------------
__device__ float g_A1[NN*HH];
__device__ float g_A2[NN*HH];
__device__ float g_H3[NN*FF];
__device__ float g_p1s[256*HH], g_p1q[256*HH];   // node1 per-block stats partials
__device__ float g_p2s[256*HH], g_p2q[256*HH];   // node2 per-block stats partials
__device__ double g_s5[HH], g_q5[HH];
// t-cache, column-planar: g_Tc[c2*ES + edge_slot], half2 per u32. 545 MB.
// invalid (diagonal jj<=ii) slots hold 0 so plain sums give valid-edge stats.
__device__ u32 g_Tc[64*ES];

__device__ __forceinline__ float lrelu(float x){ return fmaxf(x, 0.01f*x); }

// ---------------- node layer 1: 256 blocks x 8 rows, partial stats ----------------
__global__ void k_node1(const float* __restrict__ nf, const float* __restrict__ W1,
                        const float* __restrict__ b1){
  __shared__ float nfs[8*FF];
  int tid = threadIdx.x;
  int r0  = blockIdx.x*8;
  for (int i = tid; i < 8*FF; i += 128) nfs[i] = nf[r0*FF + i];
  float w[FF];
  #pragma unroll
  for (int k = 0; k < FF; k++) w[k] = W1[k*HH + tid];
  float bc = b1[tid];
  __syncthreads();
  float s = 0.f, q = 0.f;
  #pragma unroll
  for (int r = 0; r < 8; r++){
    float a0=0.f, a1=0.f, a2=0.f, a3=0.f;
    #pragma unroll
    for (int k = 0; k < FF; k += 4){
      a0 += nfs[r*FF+k]*w[k];
      a1 += nfs[r*FF+k+1]*w[k+1];
      a2 += nfs[r*FF+k+2]*w[k+2];
      a3 += nfs[r*FF+k+3]*w[k+3];
    }
    float a = lrelu(bc + (a0+a1) + (a2+a3));
    g_A1[(r0+r)*HH + tid] = a;
    s += a; q += a*a;
  }
  g_p1s[blockIdx.x*HH + tid] = s;
  g_p1q[blockIdx.x*HH + tid] = q;
}

// ---------------- node layer 2: in-block BN1 fold, partial stats ----------------
__global__ void k_node2(const float* __restrict__ W2, const float* __restrict__ b2,
                        const float* __restrict__ g1, const float* __restrict__ be1){
  extern __shared__ float sm2[];
  float* w2s = sm2;                 // 16384 (folded)
  float* a1s = sm2 + HH*HH;         // 1024
  float* al  = a1s + 8*HH;          // 128
  float* bt  = al + HH;             // 128
  int tid = threadIdx.x;
  int r0  = blockIdx.x*8;

  // reduce node1 partials (all blocks redundantly; L2-resident)
  {
    float s = 0.f, q = 0.f;
    #pragma unroll 4
    for (int b = 0; b < 256; b++){
      s += g_p1s[b*HH + tid];
      q += g_p1q[b*HH + tid];
    }
    float m = s/(float)NN;
    float v = q/(float)NN - m*m;
    float a = rsqrtf(v + 1e-5f) * g1[tid];
    al[tid] = a;
    bt[tid] = be1[tid] - m*a;
  }
  __syncthreads();

  // stage folded W2, A1 rows, and folded bias
  for (int i = tid; i < HH*HH; i += 128){
    int k = i >> 7;
    w2s[i] = al[k]*W2[i];
  }
  for (int i = tid; i < 8*HH; i += 128) a1s[i] = g_A1[r0*HH + i];
  float bc = b2[tid];
  for (int k = 0; k < HH; k++) bc += bt[k]*W2[k*HH + tid];
  __syncthreads();

  float acc[8];
  #pragma unroll
  for (int r = 0; r < 8; r++) acc[r] = 0.f;
  for (int kb = 0; kb < HH; kb += 8){
    float w0 = w2s[(kb+0)*HH+tid], w1 = w2s[(kb+1)*HH+tid];
    float w2_ = w2s[(kb+2)*HH+tid], w3 = w2s[(kb+3)*HH+tid];
    float w4 = w2s[(kb+4)*HH+tid], w5 = w2s[(kb+5)*HH+tid];
    float w6 = w2s[(kb+6)*HH+tid], w7 = w2s[(kb+7)*HH+tid];
    #pragma unroll
    for (int r = 0; r < 8; r++){
      const float* ar = a1s + r*HH + kb;
      float p0 = ar[0]*w0 + ar[1]*w1;
      float p1 = ar[2]*w2_ + ar[3]*w3;
      float p2 = ar[4]*w4 + ar[5]*w5;
      float p3 = ar[6]*w6 + ar[7]*w7;
      acc[r] += (p0+p1) + (p2+p3);
    }
  }
  float s = 0.f, q = 0.f;
  #pragma unroll
  for (int r = 0; r < 8; r++){
    float a = lrelu(acc[r] + bc);
    g_A2[(r0+r)*HH + tid] = a;
    s += a; q += a*a;
  }
  g_p2s[blockIdx.x*HH + tid] = s;
  g_p2q[blockIdx.x*HH + tid] = q;
}

// ---------------- node layer 3: in-block BN2 fold, residual ----------------
__global__ void k_node3(const float* __restrict__ nf, const float* __restrict__ W3,
                        const float* __restrict__ b3, const float* __restrict__ g2,
                        const float* __restrict__ be2){
  __shared__ float a2s[8*HH];     // 4KB
  __shared__ float w3s[HH*FF];    // 32KB
  __shared__ float al2[HH], bt2[HH];
  int tid = threadIdx.x;
  int r0  = blockIdx.x*8;

  {
    float s = 0.f, q = 0.f;
    #pragma unroll 4
    for (int b = 0; b < 256; b++){
      s += g_p2s[b*HH + tid];
      q += g_p2q[b*HH + tid];
    }
    float m = s/(float)NN;
    float v = q/(float)NN - m*m;
    float a = rsqrtf(v + 1e-5f) * g2[tid];
    al2[tid] = a;
    bt2[tid] = be2[tid] - m*a;
  }
  __syncthreads();

  for (int i = tid; i < 8*HH; i += 128) a2s[i] = g_A2[r0*HH + i];
  for (int i = tid; i < HH*FF; i += 128){
    int k = i >> 6;
    w3s[i] = al2[k]*W3[i];
  }
  int c = tid & 63, rh = tid >> 6;
  float bf = b3[c];
  for (int k = 0; k < HH; k++) bf += bt2[k]*W3[k*FF + c];
  __syncthreads();

  float acc[4];
  #pragma unroll
  for (int r = 0; r < 4; r++) acc[r] = 0.f;
  for (int kb = 0; kb < HH; kb += 8){
    float w0 = w3s[(kb+0)*FF+c], w1 = w3s[(kb+1)*FF+c];
    float w2 = w3s[(kb+2)*FF+c], w3_ = w3s[(kb+3)*FF+c];
    float w4 = w3s[(kb+4)*FF+c], w5 = w3s[(kb+5)*FF+c];
    float w6 = w3s[(kb+6)*FF+c], w7 = w3s[(kb+7)*FF+c];
    #pragma unroll
    for (int r = 0; r < 4; r++){
      const float* ar = a2s + (rh*4+r)*HH + kb;
      float p0 = ar[0]*w0 + ar[1]*w1;
      float p1 = ar[2]*w2 + ar[3]*w3_;
      float p2 = ar[4]*w4 + ar[5]*w5;
      float p3 = ar[6]*w6 + ar[7]*w7;
      acc[r] += (p0+p1) + (p2+p3);
    }
  }
  #pragma unroll
  for (int r = 0; r < 4; r++){
    int rr = rh*4 + r;
    g_H3[(r0+rr)*FF + c] = acc[r] + bf + nf[(r0+rr)*FF + c];
  }
}

// ---------------- edge pass 1: fp16 mma m16n8k16, no stats, 2 blocks/SM ----------------
// SMEM floats: W5f 5120 | Hi 32*72=2304 | Hj 2304 | b5s 128 = 9856 floats
#define H_STR   72
#define OFF_W5F 0
#define OFF_HI  5120
#define OFF_HJ  (OFF_HI+2304)
#define OFF_B5  (OFF_HJ+2304)
#define EDGE1_SMEM ((OFF_B5 + 128)*4)   // 39424 bytes

__global__ void __launch_bounds__(256, 2)
k_edgeG(const float* __restrict__ W5, const float* __restrict__ b5){
  extern __shared__ float sm[];
  u32*   w5f = (u32*)(sm + OFF_W5F);      // fragment-order B, lane stride 20 u32
  float* Hi  = sm + OFF_HI;
  float* Hj  = sm + OFF_HJ;
  float* b5s = sm + OFF_B5;

  int tid = threadIdx.x;
  int lane = tid & 31, wid = tid >> 5;
  int mg = wid & 3, ng = wid >> 2;
  int qid = lane >> 2, qlane = lane & 3;

  int p = blockIdx.x, bi = 0, rem = p;
  while (rem >= NB - bi){ rem -= NB - bi; bi++; }
  int bj = bi + rem;

  // zero BN5 stats accumulators (consumed by k_stats after this kernel)
  if (p == 0 && tid < HH){ g_s5[tid] = 0.0; g_q5[tid] = 0.0; }

  // stage B fragments: b = half2(W5[k][n], W5[k+1][n]), k = ks*16 + ql*2 + w*8,
  // n = g*64 + nt*8 + qi; layout (g*4+ks, lane)*20 + nt*2+w
  for (int idx = tid; idx < 4096; idx += 256){
    int g  = idx >> 11;
    int ks = (idx >> 9) & 3;
    int ln = (idx >> 4) & 31;
    int f  = idx & 15;
    int qi = ln >> 2, ql = ln & 3;
    int nt = f >> 1, w = f & 1;
    int k = ks*16 + ql*2 + w*8;
    int n = g*64 + nt*8 + qi;
    __half2 hv = __floats2half2_rn(W5[k*HH + n], W5[(k+1)*HH + n]);
    w5f[((g*4 + ks)*32 + ln)*20 + f] = *(u32*)&hv;
  }
  for (int i = tid; i < TI*FF; i += 256){
    int r = i >> 6, k = i & 63;
    Hi[r*H_STR + k] = g_H3[(bi*TI + r)*FF + k];
    Hj[r*H_STR + k] = g_H3[(bj*TI + r)*FF + k];
  }
  if (tid < HH) b5s[tid] = b5[tid];
  __syncthreads();
  // ---- mainloop: NO barriers below (all smem read-only) ----

  size_t pbase = (size_t)p*1024;
  bool offdiag = (bi != bj);

  for (int t = 0; t < 8; t++){
    float acc[2][8][4];
    #pragma unroll
    for (int mt = 0; mt < 2; mt++)
      #pragma unroll
      for (int nt = 0; nt < 8; nt++)
        #pragma unroll
        for (int c = 0; c < 4; c++) acc[mt][nt][c] = 0.f;

    int ii = t*4 + mg;
    const float2* HiR = (const float2*)(Hi + ii*H_STR);

    #pragma unroll
    for (int ks = 0; ks < 4; ks++){
      const uint4* Bp = (const uint4*)(w5f + ((ng*4 + ks)*32 + lane)*20);
      uint4 B0 = Bp[0], B1 = Bp[1], B2 = Bp[2], B3 = Bp[3];
      u32 b[16] = {B0.x,B0.y,B0.z,B0.w, B1.x,B1.y,B1.z,B1.w,
                   B2.x,B2.y,B2.z,B2.w, B3.x,B3.y,B3.z,B3.w};
      int c2 = ks*8 + qlane;
      float2 hiA = HiR[c2], hiB = HiR[c2+4];
      #pragma unroll
      for (int mt = 0; mt < 2; mt++){
        const float2* HjA = (const float2*)(Hj + (mt*16 + qid)*H_STR);
        const float2* HjB = (const float2*)(Hj + (mt*16 + qid + 8)*H_STR);
        float2 jA  = HjA[c2], jB  = HjB[c2];
        float2 jA2 = HjA[c2+4], jB2 = HjB[c2+4];
        __half2 a0h = __floats2half2_rn(hiA.x*jA.x,  hiA.y*jA.y);
        __half2 a1h = __floats2half2_rn(hiA.x*jB.x,  hiA.y*jB.y);
        __half2 a2h = __floats2half2_rn(hiB.x*jA2.x, hiB.y*jA2.y);
        __half2 a3h = __floats2half2_rn(hiB.x*jB2.x, hiB.y*jB2.y);
        u32 a0 = *(u32*)&a0h, a1 = *(u32*)&a1h, a2 = *(u32*)&a2h, a3 = *(u32*)&a3h;
        #pragma unroll
        for (int nt = 0; nt < 8; nt++){
          asm volatile(
            "mma.sync.aligned.m16n8k16.row.col.f32.f16.f16.f32 "
            "{%0,%1,%2,%3},{%4,%5,%6,%7},{%8,%9},{%0,%1,%2,%3};"
            : "+f"(acc[mt][nt][0]), "+f"(acc[mt][nt][1]),
              "+f"(acc[mt][nt][2]), "+f"(acc[mt][nt][3])
            : "r"(a0),"r"(a1),"r"(a2),"r"(a3), "r"(b[2*nt]),"r"(b[2*nt+1]));
        }
      }
    }

    // epilogue: lrelu + bias, direct fp16 store; invalid diagonal slots get 0
    size_t tbase = pbase + (size_t)t*128 + mg*32;
    #pragma unroll
    for (int nt = 0; nt < 8; nt++){
      float2 bb = *(const float2*)&b5s[ng*64 + nt*8 + qlane*2];
      int c2 = ng*32 + nt*4 + qlane;
      u32* colp = g_Tc + (size_t)c2*ES + tbase;
      #pragma unroll
      for (int mt = 0; mt < 2; mt++)
        #pragma unroll
        for (int h = 0; h < 2; h++){
          float tv0 = lrelu(acc[mt][nt][2*h]   + bb.x);
          float tv1 = lrelu(acc[mt][nt][2*h+1] + bb.y);
          int jj = mt*16 + qid + h*8;
          __half2 hv = __floats2half2_rn(tv0, tv1);
          u32 word = (offdiag || (jj > ii)) ? *(u32*)&hv : 0u;
          colp[jj] = word;
        }
    }
  }
}

// ---------------- stats over t-cache (invalid slots are 0) ----------------
__global__ void __launch_bounds__(256)
k_stats(){
  __shared__ float rs[4*8];
  int blk = blockIdx.x;                 // 256 blocks
  int c2 = blk >> 2, quad = blk & 3;
  const uint4* ptr = (const uint4*)(g_Tc + (size_t)c2*ES + (size_t)quad*(ES/4));
  const int n4 = (int)(ES/4/4);         // 133120
  int tid = threadIdx.x;
  float s0=0.f, q0=0.f, s1=0.f, q1=0.f;
  for (int i = tid; i < n4; i += 256){
    uint4 v = ptr[i];
    float2 f0 = __half22float2(*(__half2*)&v.x);
    float2 f1 = __half22float2(*(__half2*)&v.y);
    float2 f2 = __half22float2(*(__half2*)&v.z);
    float2 f3 = __half22float2(*(__half2*)&v.w);
    s0 += (f0.x + f1.x) + (f2.x + f3.x);
    s1 += (f0.y + f1.y) + (f2.y + f3.y);
    q0 += (f0.x*f0.x + f1.x*f1.x) + (f2.x*f2.x + f3.x*f3.x);
    q1 += (f0.y*f0.y + f1.y*f1.y) + (f2.y*f2.y + f3.y*f3.y);
  }
  #pragma unroll
  for (int off = 16; off >= 1; off >>= 1){
    s0 += __shfl_xor_sync(0xffffffffu, s0, off);
    s1 += __shfl_xor_sync(0xffffffffu, s1, off);
    q0 += __shfl_xor_sync(0xffffffffu, q0, off);
    q1 += __shfl_xor_sync(0xffffffffu, q1, off);
  }
  int wid = tid >> 5;
  if ((tid & 31) == 0){
    rs[wid] = s0; rs[8 + wid] = s1; rs[16 + wid] = q0; rs[24 + wid] = q1;
  }
  __syncthreads();
  if (tid == 0){
    float a0=0.f, a1=0.f, b0=0.f, b1=0.f;
    #pragma unroll
    for (int w = 0; w < 8; w++){ a0+=rs[w]; a1+=rs[8+w]; b0+=rs[16+w]; b1+=rs[24+w]; }
    atomicAdd(&g_s5[2*c2],   (double)a0);
    atomicAdd(&g_s5[2*c2+1], (double)a1);
    atomicAdd(&g_q5[2*c2],   (double)b0);
    atomicAdd(&g_q5[2*c2+1], (double)b1);
  }
}

// ---------------- edge pass 2: in-block BN5 fold, coalesced dual-orientation writes ----------------
__global__ void __launch_bounds__(256)
k_edge2h(const float* __restrict__ W6, const float* __restrict__ b6,
         const float* __restrict__ g5, const float* __restrict__ be5,
         float* __restrict__ out){
  __shared__ float w0s[HH], w1s[HH], bts[HH], scal[2];
  __shared__ float2 prs[32*33];
  int tid = threadIdx.x;
  if (tid < HH){
    double md = g_s5[tid]/EDGEF;
    double vd = g_q5[tid]/EDGEF - md*md;
    float a = rsqrtf((float)vd + 1e-5f) * g5[tid];
    bts[tid] = be5[tid] - (float)md*a;
    w0s[tid] = a*W6[tid*2];
    w1s[tid] = a*W6[tid*2 + 1];
  }
  __syncthreads();
  if (tid < 32){
    float t0 = 0.f, t1 = 0.f;
    for (int k = tid; k < HH; k += 32){
      t0 += bts[k]*W6[k*2];
      t1 += bts[k]*W6[k*2 + 1];
    }
    #pragma unroll
    for (int off = 16; off >= 1; off >>= 1){
      t0 += __shfl_xor_sync(0xffffffffu, t0, off);
      t1 += __shfl_xor_sync(0xffffffffu, t1, off);
    }
    if (tid == 0){ scal[0] = b6[0] + t0; scal[1] = b6[1] + t1; }
  }
  int p = blockIdx.x;
  int bi = 0, rem = p;
  while (rem >= NB - bi){ rem -= NB - bi; bi++; }
  int bj = bi + rem;
  __syncthreads();
  float b60 = scal[0], b61 = scal[1];

  #pragma unroll
  for (int s4 = 0; s4 < 4; s4++){
    int slot = s4*256 + tid;
    size_t base = (size_t)p*1024 + slot;
    float l0 = b60, l1 = b61;
    #pragma unroll 8
    for (int c2 = 0; c2 < 64; c2++){
      u32 v = g_Tc[(size_t)c2*ES + base];
      float2 f = __half22float2(*(__half2*)&v);
      l0 += f.x*w0s[2*c2] + f.y*w0s[2*c2+1];
      l1 += f.x*w1s[2*c2] + f.y*w1s[2*c2+1];
    }
    float q = __expf(l1 - l0);
    float inv = 1.f/(1.f + q);
    int ii = slot >> 5, jj = slot & 31;
    prs[ii*33 + jj] = make_float2(inv, q*inv);
  }
  __syncthreads();

  float2* o2 = (float2*)out;
  size_t rowi = (size_t)(bi*TI)*NN + bj*TI;
  size_t rowj = (size_t)(bj*TI)*NN + bi*TI;
  if (bi != bj){
    #pragma unroll
    for (int s4 = 0; s4 < 4; s4++){
      int idx = s4*256 + tid;
      int ii = idx >> 5, jj = idx & 31;
      o2[rowi + (size_t)ii*NN + jj] = prs[ii*33 + jj];
    }
    #pragma unroll
    for (int s4 = 0; s4 < 4; s4++){
      int idx = s4*256 + tid;
      int jj = idx >> 5, ii = idx & 31;
      o2[rowj + (size_t)jj*NN + ii] = prs[ii*33 + jj];
    }
  } else {
    #pragma unroll
    for (int s4 = 0; s4 < 4; s4++){
      int idx = s4*256 + tid;
      int ii = idx >> 5, jj = idx & 31;
      if (jj > ii) o2[rowi + (size_t)ii*NN + jj] = prs[ii*33 + jj];
    }
    #pragma unroll
    for (int s4 = 0; s4 < 4; s4++){
      int idx = s4*256 + tid;
      int jj = idx >> 5, ii = idx & 31;
      if (jj > ii) o2[rowj + (size_t)jj*NN + ii] = prs[ii*33 + jj];
    }
    if (tid < 32) o2[rowi + (size_t)tid*NN + tid] = make_float2(0.f, 0.f);
  }
}

// ---------------- launch ----------------
extern "C" void kernel_launch(void* const* d_in, const int* in_sizes, int n_in,
                              void* d_out, int out_size){
  const float* nf  = (const float*)d_in[1];
  const float* W1  = (const float*)d_in[2];
  const float* b1  = (const float*)d_in[3];
  const float* g1  = (const float*)d_in[4];
  const float* be1 = (const float*)d_in[5];
  const float* W2  = (const float*)d_in[6];
  const float* b2  = (const float*)d_in[7];
  const float* g2  = (const float*)d_in[8];
  const float* be2 = (const float*)d_in[9];
  const float* W3  = (const float*)d_in[10];
  const float* b3  = (const float*)d_in[11];
  const float* W5  = (const float*)d_in[12];
  const float* b5  = (const float*)d_in[13];
  const float* g5  = (const float*)d_in[14];
  const float* be5 = (const float*)d_in[15];
  const float* W6  = (const float*)d_in[16];
  const float* b6  = (const float*)d_in[17];
  float* out = (float*)d_out;

  const int N2_SMEM = (HH*HH + 8*HH + 2*HH) * 4;
  cudaFuncSetAttribute(k_node2, cudaFuncAttributeMaxDynamicSharedMemorySize, N2_SMEM);
  cudaFuncSetAttribute(k_edgeG, cudaFuncAttributeMaxDynamicSharedMemorySize, EDGE1_SMEM);

  k_node1<<<256, 128>>>(nf, W1, b1);
  k_node2<<<256, 128, N2_SMEM>>>(W2, b2, g1, be1);
  k_node3<<<256, 128>>>(nf, W3, b3, g2, be2);
  k_edgeG<<<NPAIR, 256, EDGE1_SMEM>>>(W5, b5);
  k_stats<<<256, 256>>>();
  k_edge2h<<<NPAIR, 256>>>(W6, b6, g5, be5, out);
}